// round 1
// baseline (speedup 1.0000x reference)
#include <cuda_runtime.h>
#include <math.h>
#include <stdint.h>

// Problem dims
#define SEQ   2048
#define DIN   2048
#define NH    16
#define NG    4
#define GSZ   4          // NH / NG
#define HD    128
#define NTOK  4096       // B * SEQ
#define QSCALE 0.08838834764831843f   // 128^-0.5

// ---------------- scratch (device globals; no allocation allowed) -------------
__device__ float g_q[(size_t)NTOK * (NH * HD)];    // 32 MB
__device__ float g_k[(size_t)NTOK * (NG * HD)];    // 8 MB
__device__ float g_v[(size_t)NTOK * (NG * HD)];    // 8 MB
__device__ float g_ctx[(size_t)NTOK * (NH * HD)];  // 32 MB

// ---------------- fp32 tiled SGEMM:  C[M,N] = A[M,K] @ B[K,N], all row-major --
// BM=BN=128, BK=8, TM=TN=8, 256 threads. M,N,K assumed multiples of tile dims.
__global__ __launch_bounds__(256) void sgemm_kernel(
    const float* __restrict__ A, const float* __restrict__ B,
    float* __restrict__ C, int M, int N, int K)
{
    __shared__ float As[8][128];
    __shared__ float Bs[8][128];

    const int tid = threadIdx.x;
    const int bx = blockIdx.x;     // N tile
    const int by = blockIdx.y;     // M tile

    const int row_c = (tid >> 4) * 8;   // 0..120
    const int col_c = (tid & 15) * 8;   // 0..120

    const int a_r = tid >> 1;           // 0..127
    const int a_c = (tid & 1) * 4;      // 0 or 4
    const int b_r = tid >> 5;           // 0..7
    const int b_c = (tid & 31) * 4;     // 0..124

    const float* Ab = A + (size_t)(by * 128) * K;
    const float* Bb = B + bx * 128;

    float acc[8][8];
#pragma unroll
    for (int i = 0; i < 8; i++)
#pragma unroll
        for (int j = 0; j < 8; j++) acc[i][j] = 0.f;

    for (int k0 = 0; k0 < K; k0 += 8) {
        float4 av = *(const float4*)(Ab + (size_t)a_r * K + k0 + a_c);
        As[a_c + 0][a_r] = av.x;
        As[a_c + 1][a_r] = av.y;
        As[a_c + 2][a_r] = av.z;
        As[a_c + 3][a_r] = av.w;
        *(float4*)(&Bs[b_r][b_c]) = *(const float4*)(Bb + (size_t)(k0 + b_r) * N + b_c);
        __syncthreads();

#pragma unroll
        for (int kk = 0; kk < 8; kk++) {
            float ar[8], br[8];
            *(float4*)(ar)     = *(const float4*)(&As[kk][row_c]);
            *(float4*)(ar + 4) = *(const float4*)(&As[kk][row_c + 4]);
            *(float4*)(br)     = *(const float4*)(&Bs[kk][col_c]);
            *(float4*)(br + 4) = *(const float4*)(&Bs[kk][col_c + 4]);
#pragma unroll
            for (int i = 0; i < 8; i++)
#pragma unroll
                for (int j = 0; j < 8; j++)
                    acc[i][j] = fmaf(ar[i], br[j], acc[i][j]);
        }
        __syncthreads();
    }

    float* Cb = C + (size_t)(by * 128 + row_c) * N + bx * 128 + col_c;
#pragma unroll
    for (int i = 0; i < 8; i++) {
#pragma unroll
        for (int j = 0; j < 8; j += 4) {
            float4 v = make_float4(acc[i][j], acc[i][j + 1], acc[i][j + 2], acc[i][j + 3]);
            *(float4*)(Cb + (size_t)i * N + j) = v;
        }
    }
}

// ---------------- fused RMSNorm + RoPE (+ optional scale), in place ----------
// grid: (NTOK, heads), block: 128 threads (one per dim)
__global__ __launch_bounds__(128) void rmsrope_kernel(
    float* __restrict__ x, const float* __restrict__ w,
    const float* __restrict__ cosb, const float* __restrict__ sinb,
    int rowstride, float outscale)
{
    const int tok = blockIdx.x;
    const int h = blockIdx.y;
    const int d = threadIdx.x;
    const int s = tok & (SEQ - 1);

    float* p = x + (size_t)tok * rowstride + h * HD;
    float v = p[d];

    float ss = v * v;
#pragma unroll
    for (int o = 16; o > 0; o >>= 1) ss += __shfl_xor_sync(0xffffffffu, ss, o);

    __shared__ float partial[4];
    __shared__ float sn[HD];
    if ((d & 31) == 0) partial[d >> 5] = ss;
    __syncthreads();
    float tot = partial[0] + partial[1] + partial[2] + partial[3];
    float rstd = rsqrtf(tot * (1.0f / HD) + 1e-6f);

    float nv = v * rstd * w[d];
    sn[d] = nv;
    __syncthreads();
    float other = sn[d ^ 64];

    float c  = cosb[(size_t)s * HD + d];
    float si = sinb[(size_t)s * HD + d];
    float outv = (d < 64) ? (nv * c - other * si) : (nv * c + other * si);
    p[d] = outv * outscale;
}

// ---------------- causal GQA flash attention (fp32) --------------------------
// grid: (SEQ/64, NH, B). 256 threads. BQ = BKT = 64.
#define BQ  64
#define BKT 64
#define SKP 132   // padded row stride (floats) for sQ/sK/sV: conflict-free LDS.128
#define SSP 65    // padded stride for score tile

#define ATTN_SMEM (((BQ * SKP) * 3 + BQ * SSP) * 4)   // 118016 bytes

__global__ __launch_bounds__(256) void attn_kernel(
    const float* __restrict__ q, const float* __restrict__ k,
    const float* __restrict__ v, float* __restrict__ out)
{
    extern __shared__ float sm[];
    float* sQ = sm;
    float* sK = sQ + BQ * SKP;
    float* sV = sK + BKT * SKP;
    float* sS = sV + BKT * SKP;

    const int tid = threadIdx.x;
    const int qt = blockIdx.x;
    const int h  = blockIdx.y;
    const int b  = blockIdx.z;
    const int g  = h / GSZ;
    const int qbase = qt * BQ;

    const float* qp = q + (size_t)b * SEQ * (NH * HD) + h * HD;   // row stride NH*HD
    const float* kp = k + (size_t)b * SEQ * (NG * HD) + g * HD;   // row stride NG*HD
    const float* vp = v + (size_t)b * SEQ * (NG * HD) + g * HD;

    // load Q tile (64 x 128)
    for (int idx = tid; idx < BQ * 32; idx += 256) {
        int r = idx >> 5, c4 = (idx & 31) * 4;
        *(float4*)(sQ + r * SKP + c4) =
            *(const float4*)(qp + (size_t)(qbase + r) * (NH * HD) + c4);
    }

    // output / softmax mapping: row oi = tid/4, col slice oc = tid%4 (32 dims)
    const int oi = tid >> 2;
    const int oc = tid & 3;
    // score mapping: 4x4 block per thread
    const int si = (tid >> 4) * 4;
    const int sj = (tid & 15) * 4;

    float acc[32];
#pragma unroll
    for (int x = 0; x < 32; x++) acc[x] = 0.f;
    float m = -1e30f, l = 0.f;

    const int ntiles = qt + 1;
    for (int kt = 0; kt < ntiles; kt++) {
        const int kbase = kt * BKT;
        __syncthreads();   // previous PV done before overwriting sK/sV (also covers sQ 1st iter)
        for (int idx = tid; idx < BKT * 32; idx += 256) {
            int r = idx >> 5, c4 = (idx & 31) * 4;
            *(float4*)(sK + r * SKP + c4) =
                *(const float4*)(kp + (size_t)(kbase + r) * (NG * HD) + c4);
            *(float4*)(sV + r * SKP + c4) =
                *(const float4*)(vp + (size_t)(kbase + r) * (NG * HD) + c4);
        }
        __syncthreads();

        // scores: 4x4 per thread over d=0..127
        float sc[4][4];
#pragma unroll
        for (int ii = 0; ii < 4; ii++)
#pragma unroll
            for (int jj = 0; jj < 4; jj++) sc[ii][jj] = 0.f;

        for (int d4 = 0; d4 < 32; d4++) {
            float4 qv[4], kv[4];
#pragma unroll
            for (int ii = 0; ii < 4; ii++) qv[ii] = *(float4*)(sQ + (si + ii) * SKP + d4 * 4);
#pragma unroll
            for (int jj = 0; jj < 4; jj++) kv[jj] = *(float4*)(sK + (sj + jj) * SKP + d4 * 4);
#pragma unroll
            for (int ii = 0; ii < 4; ii++)
#pragma unroll
                for (int jj = 0; jj < 4; jj++) {
                    sc[ii][jj] = fmaf(qv[ii].x, kv[jj].x, sc[ii][jj]);
                    sc[ii][jj] = fmaf(qv[ii].y, kv[jj].y, sc[ii][jj]);
                    sc[ii][jj] = fmaf(qv[ii].z, kv[jj].z, sc[ii][jj]);
                    sc[ii][jj] = fmaf(qv[ii].w, kv[jj].w, sc[ii][jj]);
                }
        }
        const bool diag = (kt == qt);
#pragma unroll
        for (int ii = 0; ii < 4; ii++)
#pragma unroll
            for (int jj = 0; jj < 4; jj++) {
                float val = sc[ii][jj];
                if (diag && (sj + jj > si + ii)) val = -1e30f;
                sS[(si + ii) * SSP + sj + jj] = val;
            }
        __syncthreads();

        // online softmax: each thread owns row oi, cols [oc*16, oc*16+16)
        float srow[16];
        float tmax = -1e30f;
#pragma unroll
        for (int j = 0; j < 16; j++) {
            srow[j] = sS[oi * SSP + oc * 16 + j];
            tmax = fmaxf(tmax, srow[j]);
        }
#pragma unroll
        for (int off = 1; off < 4; off <<= 1)
            tmax = fmaxf(tmax, __shfl_xor_sync(0xffffffffu, tmax, off));
        float newm = fmaxf(m, tmax);
        float psum = 0.f;
#pragma unroll
        for (int j = 0; j < 16; j++) {
            float p = __expf(srow[j] - newm);
            psum += p;
            sS[oi * SSP + oc * 16 + j] = p;
        }
#pragma unroll
        for (int off = 1; off < 4; off <<= 1)
            psum += __shfl_xor_sync(0xffffffffu, psum, off);
        float alpha = __expf(m - newm);
        l = l * alpha + psum;
        m = newm;
#pragma unroll
        for (int x = 0; x < 32; x++) acc[x] *= alpha;
        __syncthreads();

        // PV: acc[dd] += sum_j p[oi][j] * v[j][oc*32 + dd]
#pragma unroll 4
        for (int j = 0; j < BKT; j++) {
            float p = sS[oi * SSP + j];
            const float* vr = sV + j * SKP + oc * 32;
#pragma unroll
            for (int dd = 0; dd < 32; dd += 4) {
                float4 vv = *(float4*)(vr + dd);
                acc[dd + 0] = fmaf(p, vv.x, acc[dd + 0]);
                acc[dd + 1] = fmaf(p, vv.y, acc[dd + 1]);
                acc[dd + 2] = fmaf(p, vv.z, acc[dd + 2]);
                acc[dd + 3] = fmaf(p, vv.w, acc[dd + 3]);
            }
        }
    }

    const float linv = 1.0f / l;
    float* op = out + ((size_t)b * SEQ + qbase + oi) * (NH * HD) + h * HD + oc * 32;
#pragma unroll
    for (int dd = 0; dd < 32; dd += 4) {
        float4 vv = make_float4(acc[dd] * linv, acc[dd + 1] * linv,
                                acc[dd + 2] * linv, acc[dd + 3] * linv);
        *(float4*)(op + dd) = vv;
    }
}

// ---------------- launch -----------------------------------------------------
extern "C" void kernel_launch(void* const* d_in, const int* in_sizes, int n_in,
                              void* d_out, int out_size)
{
    const float* x    = (const float*)d_in[0];
    // d_in[1] = mask (causal, implicit in kernel)
    const float* cosb = (const float*)d_in[2];
    const float* sinb = (const float*)d_in[3];
    const float* Wq   = (const float*)d_in[4];
    const float* Wk   = (const float*)d_in[5];
    const float* Wv   = (const float*)d_in[6];
    const float* Wo   = (const float*)d_in[7];
    const float* qw   = (const float*)d_in[8];
    const float* kw   = (const float*)d_in[9];
    float* out = (float*)d_out;

    void *qp, *kp, *vp, *cp;
    cudaGetSymbolAddress(&qp, g_q);
    cudaGetSymbolAddress(&kp, g_k);
    cudaGetSymbolAddress(&vp, g_v);
    cudaGetSymbolAddress(&cp, g_ctx);

    // QKV projections
    sgemm_kernel<<<dim3(DIN / 128, NTOK / 128), 256>>>(x, Wq, (float*)qp, NTOK, NH * HD, DIN);
    sgemm_kernel<<<dim3((NG * HD) / 128, NTOK / 128), 256>>>(x, Wk, (float*)kp, NTOK, NG * HD, DIN);
    sgemm_kernel<<<dim3((NG * HD) / 128, NTOK / 128), 256>>>(x, Wv, (float*)vp, NTOK, NG * HD, DIN);

    // RMSNorm + RoPE (+ q scale)
    rmsrope_kernel<<<dim3(NTOK, NH), 128>>>((float*)qp, qw, cosb, sinb, NH * HD, QSCALE);
    rmsrope_kernel<<<dim3(NTOK, NG), 128>>>((float*)kp, kw, cosb, sinb, NG * HD, 1.0f);

    // flash attention
    cudaFuncSetAttribute(attn_kernel, cudaFuncAttributeMaxDynamicSharedMemorySize, ATTN_SMEM);
    attn_kernel<<<dim3(SEQ / BQ, NH, 2), 256, ATTN_SMEM>>>(
        (const float*)qp, (const float*)kp, (const float*)vp, (float*)cp);

    // output projection
    sgemm_kernel<<<dim3(DIN / 128, NTOK / 128), 256>>>((const float*)cp, Wo, out, NTOK, NH * HD, DIN);
}

// round 3
// speedup vs baseline: 1.2771x; 1.2771x over previous
#include <cuda_runtime.h>
#include <math.h>
#include <stdint.h>

// Problem dims
#define SEQ   2048
#define DIN   2048
#define NH    16
#define NG    4
#define GSZ   4          // NH / NG
#define HD    128
#define NTOK  4096       // B * SEQ
#define QSCALE 0.08838834764831843f   // 128^-0.5

// ---------------- scratch (device globals; no allocation allowed) -------------
__device__ float g_q[(size_t)NTOK * (NH * HD)];    // 32 MB
__device__ float g_k[(size_t)NTOK * (NG * HD)];    // 8 MB
__device__ float g_v[(size_t)NTOK * (NG * HD)];    // 8 MB
__device__ float g_ctx[(size_t)NTOK * (NH * HD)];  // 32 MB

// =============================================================================
// TF32 tensor-core GEMM:  C[M,N] = A[M,K] @ B[K,N], row-major fp32 in/out.
// BM=BN=128, BK=32, 256 threads = 8 warps (4M x 2N), warp tile 32x64,
// mma.sync m16n8k8 tf32, fp32 accum. Inputs rounded to tf32 with cvt.rna
// during the smem-store stage. Double-buffered smem, register prefetch.
// A smem: m-major stride 36  -> a-frag LDS bank (4r+c)%32, conflict-free.
// B smem: k-major stride 136 -> b-frag LDS bank (8c+r)%32, conflict-free.
// =============================================================================
#define AS_STRIDE 36
#define BS_STRIDE 136
#define AS_ELEMS (128 * AS_STRIDE)   // 4608 floats
#define BS_ELEMS (32 * BS_STRIDE)    // 4352 floats
#define GEMM_SMEM ((2 * AS_ELEMS + 2 * BS_ELEMS) * 4)   // 71680 bytes

__device__ __forceinline__ uint32_t f2tf32(float x) {
    uint32_t u;
    asm("cvt.rna.tf32.f32 %0, %1;" : "=r"(u) : "f"(x));
    return u;
}

#define MMA_TF32(d, a, b0, b1)                                              \
    asm volatile(                                                           \
        "mma.sync.aligned.m16n8k8.row.col.f32.tf32.tf32.f32 "               \
        "{%0,%1,%2,%3}, {%4,%5,%6,%7}, {%8,%9}, {%0,%1,%2,%3};"             \
        : "+f"(d[0]), "+f"(d[1]), "+f"(d[2]), "+f"(d[3])                    \
        : "r"(a[0]), "r"(a[1]), "r"(a[2]), "r"(a[3]), "r"(b0), "r"(b1))

__global__ __launch_bounds__(256, 1) void tf32_gemm(
    const float* __restrict__ A, const float* __restrict__ B,
    float* __restrict__ C, int M, int N, int K)
{
    extern __shared__ float sm[];
    float* As = sm;                    // [2][AS_ELEMS]
    float* Bs = sm + 2 * AS_ELEMS;     // [2][BS_ELEMS]

    const int tid  = threadIdx.x;
    const int wid  = tid >> 5;
    const int lane = tid & 31;
    const int r = lane >> 2;           // 0..7
    const int c = lane & 3;            // 0..3
    const int warp_m = wid >> 1;       // 0..3  (32 rows each)
    const int warp_n = wid & 1;        // 0..1  (64 cols each)
    const int bx = blockIdx.x, by = blockIdx.y;

    const float* gA = A + (size_t)(by * 128) * K;
    const float* gB = B + bx * 128;

    float acc[2][8][4];
#pragma unroll
    for (int mt = 0; mt < 2; mt++)
#pragma unroll
        for (int nt = 0; nt < 8; nt++)
#pragma unroll
            for (int x = 0; x < 4; x++) acc[mt][nt][x] = 0.f;

    float4 ra[4], rb[4];

    // ---- prefetch helpers (manually inlined via macros-in-loop style) ----
    // A chunk: 128 rows x 32 k -> idx = tid + i*256: row = idx>>3, kc4 = (idx&7)*4
    // B chunk: 32 k x 128 n    -> idx = tid + i*256: k = idx>>5, nc4 = (idx&31)*4
    const int nIt = K / 32;

#pragma unroll
    for (int i = 0; i < 4; i++) {
        int idx = tid + i * 256;
        ra[i] = *(const float4*)(gA + (size_t)(idx >> 3) * K + ((idx & 7) * 4));
        rb[i] = *(const float4*)(gB + (size_t)(idx >> 5) * N + ((idx & 31) * 4));
    }
    // store to buffer 0
#pragma unroll
    for (int i = 0; i < 4; i++) {
        int idx = tid + i * 256;
        {
            int row = idx >> 3, kc = (idx & 7) * 4;
            float4 v = ra[i];
            float4 w;
            w.x = __uint_as_float(f2tf32(v.x));
            w.y = __uint_as_float(f2tf32(v.y));
            w.z = __uint_as_float(f2tf32(v.z));
            w.w = __uint_as_float(f2tf32(v.w));
            *(float4*)(&As[row * AS_STRIDE + kc]) = w;
        }
        {
            int k = idx >> 5, nc = (idx & 31) * 4;
            float4 v = rb[i];
            float4 w;
            w.x = __uint_as_float(f2tf32(v.x));
            w.y = __uint_as_float(f2tf32(v.y));
            w.z = __uint_as_float(f2tf32(v.z));
            w.w = __uint_as_float(f2tf32(v.w));
            *(float4*)(&Bs[k * BS_STRIDE + nc]) = w;
        }
    }
    __syncthreads();

    for (int it = 0; it < nIt; it++) {
        const int buf = it & 1;
        if (it + 1 < nIt) {
            const int k0 = (it + 1) * 32;
#pragma unroll
            for (int i = 0; i < 4; i++) {
                int idx = tid + i * 256;
                ra[i] = *(const float4*)(gA + (size_t)(idx >> 3) * K + k0 + ((idx & 7) * 4));
                rb[i] = *(const float4*)(gB + (size_t)(k0 + (idx >> 5)) * N + ((idx & 31) * 4));
            }
        }

        const float* a_s = As + buf * AS_ELEMS;
        const float* b_s = Bs + buf * BS_ELEMS;

#pragma unroll
        for (int ks = 0; ks < 4; ks++) {
            const int kc = ks * 8 + c;
            uint32_t af[2][4];
#pragma unroll
            for (int mt = 0; mt < 2; mt++) {
                const int row0 = warp_m * 32 + mt * 16 + r;
                af[mt][0] = __float_as_uint(a_s[row0 * AS_STRIDE + kc]);
                af[mt][1] = __float_as_uint(a_s[(row0 + 8) * AS_STRIDE + kc]);
                af[mt][2] = __float_as_uint(a_s[row0 * AS_STRIDE + kc + 4]);
                af[mt][3] = __float_as_uint(a_s[(row0 + 8) * AS_STRIDE + kc + 4]);
            }
#pragma unroll
            for (int nt = 0; nt < 8; nt++) {
                const int n0 = warp_n * 64 + nt * 8 + r;
                uint32_t b0 = __float_as_uint(b_s[kc * BS_STRIDE + n0]);
                uint32_t b1 = __float_as_uint(b_s[(kc + 4) * BS_STRIDE + n0]);
                MMA_TF32(acc[0][nt], af[0], b0, b1);
                MMA_TF32(acc[1][nt], af[1], b0, b1);
            }
        }

        if (it + 1 < nIt) {
            const int nbuf = buf ^ 1;
            float* a_d = As + nbuf * AS_ELEMS;
            float* b_d = Bs + nbuf * BS_ELEMS;
#pragma unroll
            for (int i = 0; i < 4; i++) {
                int idx = tid + i * 256;
                {
                    int row = idx >> 3, kc2 = (idx & 7) * 4;
                    float4 v = ra[i];
                    float4 w;
                    w.x = __uint_as_float(f2tf32(v.x));
                    w.y = __uint_as_float(f2tf32(v.y));
                    w.z = __uint_as_float(f2tf32(v.z));
                    w.w = __uint_as_float(f2tf32(v.w));
                    *(float4*)(&a_d[row * AS_STRIDE + kc2]) = w;
                }
                {
                    int k = idx >> 5, nc = (idx & 31) * 4;
                    float4 v = rb[i];
                    float4 w;
                    w.x = __uint_as_float(f2tf32(v.x));
                    w.y = __uint_as_float(f2tf32(v.y));
                    w.z = __uint_as_float(f2tf32(v.z));
                    w.w = __uint_as_float(f2tf32(v.w));
                    *(float4*)(&b_d[k * BS_STRIDE + nc]) = w;
                }
            }
            __syncthreads();
        }
    }

    // epilogue
#pragma unroll
    for (int mt = 0; mt < 2; mt++) {
#pragma unroll
        for (int nt = 0; nt < 8; nt++) {
            const int row0 = by * 128 + warp_m * 32 + mt * 16 + r;
            const int col  = bx * 128 + warp_n * 64 + nt * 8 + 2 * c;
            float2 v0 = make_float2(acc[mt][nt][0], acc[mt][nt][1]);
            float2 v1 = make_float2(acc[mt][nt][2], acc[mt][nt][3]);
            *(float2*)(C + (size_t)row0 * N + col) = v0;
            *(float2*)(C + (size_t)(row0 + 8) * N + col) = v1;
        }
    }
}

// ---------------- fused RMSNorm + RoPE (+ optional scale), in place ----------
__global__ __launch_bounds__(128) void rmsrope_kernel(
    float* __restrict__ x, const float* __restrict__ w,
    const float* __restrict__ cosb, const float* __restrict__ sinb,
    int rowstride, float outscale)
{
    const int tok = blockIdx.x;
    const int h = blockIdx.y;
    const int d = threadIdx.x;
    const int s = tok & (SEQ - 1);

    float* p = x + (size_t)tok * rowstride + h * HD;
    float v = p[d];

    float ss = v * v;
#pragma unroll
    for (int o = 16; o > 0; o >>= 1) ss += __shfl_xor_sync(0xffffffffu, ss, o);

    __shared__ float partial[4];
    __shared__ float sn[HD];
    if ((d & 31) == 0) partial[d >> 5] = ss;
    __syncthreads();
    float tot = partial[0] + partial[1] + partial[2] + partial[3];
    float rstd = rsqrtf(tot * (1.0f / HD) + 1e-6f);

    float nv = v * rstd * w[d];
    sn[d] = nv;
    __syncthreads();
    float other = sn[d ^ 64];

    float cc = cosb[(size_t)s * HD + d];
    float si = sinb[(size_t)s * HD + d];
    float outv = (d < 64) ? (nv * cc - other * si) : (nv * cc + other * si);
    p[d] = outv * outscale;
}

// ---------------- causal GQA flash attention (fp32) --------------------------
#define BQ  64
#define BKT 64
#define SKP 132
#define SSP 65
#define ATTN_SMEM (((BQ * SKP) * 3 + BQ * SSP) * 4)

__global__ __launch_bounds__(256) void attn_kernel(
    const float* __restrict__ q, const float* __restrict__ k,
    const float* __restrict__ v, float* __restrict__ out)
{
    extern __shared__ float smf[];
    float* sQ = smf;
    float* sK = sQ + BQ * SKP;
    float* sV = sK + BKT * SKP;
    float* sS = sV + BKT * SKP;

    const int tid = threadIdx.x;
    const int qt = blockIdx.x;
    const int h  = blockIdx.y;
    const int b  = blockIdx.z;
    const int g  = h / GSZ;
    const int qbase = qt * BQ;

    const float* qp = q + (size_t)b * SEQ * (NH * HD) + h * HD;
    const float* kp = k + (size_t)b * SEQ * (NG * HD) + g * HD;
    const float* vp = v + (size_t)b * SEQ * (NG * HD) + g * HD;

    for (int idx = tid; idx < BQ * 32; idx += 256) {
        int r = idx >> 5, c4 = (idx & 31) * 4;
        *(float4*)(sQ + r * SKP + c4) =
            *(const float4*)(qp + (size_t)(qbase + r) * (NH * HD) + c4);
    }

    const int oi = tid >> 2;
    const int oc = tid & 3;
    const int si = (tid >> 4) * 4;
    const int sj = (tid & 15) * 4;

    float acc[32];
#pragma unroll
    for (int x = 0; x < 32; x++) acc[x] = 0.f;
    float m = -1e30f, l = 0.f;

    const int ntiles = qt + 1;
    for (int kt = 0; kt < ntiles; kt++) {
        const int kbase = kt * BKT;
        __syncthreads();
        for (int idx = tid; idx < BKT * 32; idx += 256) {
            int r = idx >> 5, c4 = (idx & 31) * 4;
            *(float4*)(sK + r * SKP + c4) =
                *(const float4*)(kp + (size_t)(kbase + r) * (NG * HD) + c4);
            *(float4*)(sV + r * SKP + c4) =
                *(const float4*)(vp + (size_t)(kbase + r) * (NG * HD) + c4);
        }
        __syncthreads();

        float sc[4][4];
#pragma unroll
        for (int ii = 0; ii < 4; ii++)
#pragma unroll
            for (int jj = 0; jj < 4; jj++) sc[ii][jj] = 0.f;

        for (int d4 = 0; d4 < 32; d4++) {
            float4 qv[4], kv[4];
#pragma unroll
            for (int ii = 0; ii < 4; ii++) qv[ii] = *(float4*)(sQ + (si + ii) * SKP + d4 * 4);
#pragma unroll
            for (int jj = 0; jj < 4; jj++) kv[jj] = *(float4*)(sK + (sj + jj) * SKP + d4 * 4);
#pragma unroll
            for (int ii = 0; ii < 4; ii++)
#pragma unroll
                for (int jj = 0; jj < 4; jj++) {
                    sc[ii][jj] = fmaf(qv[ii].x, kv[jj].x, sc[ii][jj]);
                    sc[ii][jj] = fmaf(qv[ii].y, kv[jj].y, sc[ii][jj]);
                    sc[ii][jj] = fmaf(qv[ii].z, kv[jj].z, sc[ii][jj]);
                    sc[ii][jj] = fmaf(qv[ii].w, kv[jj].w, sc[ii][jj]);
                }
        }
        const bool diag = (kt == qt);
#pragma unroll
        for (int ii = 0; ii < 4; ii++)
#pragma unroll
            for (int jj = 0; jj < 4; jj++) {
                float val = sc[ii][jj];
                if (diag && (sj + jj > si + ii)) val = -1e30f;
                sS[(si + ii) * SSP + sj + jj] = val;
            }
        __syncthreads();

        float srow[16];
        float tmax = -1e30f;
#pragma unroll
        for (int j = 0; j < 16; j++) {
            srow[j] = sS[oi * SSP + oc * 16 + j];
            tmax = fmaxf(tmax, srow[j]);
        }
#pragma unroll
        for (int off = 1; off < 4; off <<= 1)
            tmax = fmaxf(tmax, __shfl_xor_sync(0xffffffffu, tmax, off));
        float newm = fmaxf(m, tmax);
        float psum = 0.f;
#pragma unroll
        for (int j = 0; j < 16; j++) {
            float p = __expf(srow[j] - newm);
            psum += p;
            sS[oi * SSP + oc * 16 + j] = p;
        }
#pragma unroll
        for (int off = 1; off < 4; off <<= 1)
            psum += __shfl_xor_sync(0xffffffffu, psum, off);
        float alpha = __expf(m - newm);
        l = l * alpha + psum;
        m = newm;
#pragma unroll
        for (int x = 0; x < 32; x++) acc[x] *= alpha;
        __syncthreads();

#pragma unroll 4
        for (int j = 0; j < BKT; j++) {
            float p = sS[oi * SSP + j];
            const float* vr = sV + j * SKP + oc * 32;
#pragma unroll
            for (int dd = 0; dd < 32; dd += 4) {
                float4 vv = *(float4*)(vr + dd);
                acc[dd + 0] = fmaf(p, vv.x, acc[dd + 0]);
                acc[dd + 1] = fmaf(p, vv.y, acc[dd + 1]);
                acc[dd + 2] = fmaf(p, vv.z, acc[dd + 2]);
                acc[dd + 3] = fmaf(p, vv.w, acc[dd + 3]);
            }
        }
    }

    const float linv = 1.0f / l;
    float* op = out + ((size_t)b * SEQ + qbase + oi) * (NH * HD) + h * HD + oc * 32;
#pragma unroll
    for (int dd = 0; dd < 32; dd += 4) {
        float4 vv = make_float4(acc[dd] * linv, acc[dd + 1] * linv,
                                acc[dd + 2] * linv, acc[dd + 3] * linv);
        *(float4*)(op + dd) = vv;
    }
}

// ---------------- launch -----------------------------------------------------
extern "C" void kernel_launch(void* const* d_in, const int* in_sizes, int n_in,
                              void* d_out, int out_size)
{
    const float* x    = (const float*)d_in[0];
    // d_in[1] = mask (causal, implicit)
    const float* cosb = (const float*)d_in[2];
    const float* sinb = (const float*)d_in[3];
    const float* Wq   = (const float*)d_in[4];
    const float* Wk   = (const float*)d_in[5];
    const float* Wv   = (const float*)d_in[6];
    const float* Wo   = (const float*)d_in[7];
    const float* qw   = (const float*)d_in[8];
    const float* kw   = (const float*)d_in[9];
    float* out = (float*)d_out;

    void *qp, *kp, *vp, *cp;
    cudaGetSymbolAddress(&qp, g_q);
    cudaGetSymbolAddress(&kp, g_k);
    cudaGetSymbolAddress(&vp, g_v);
    cudaGetSymbolAddress(&cp, g_ctx);

    cudaFuncSetAttribute(tf32_gemm, cudaFuncAttributeMaxDynamicSharedMemorySize, GEMM_SMEM);
    cudaFuncSetAttribute(attn_kernel, cudaFuncAttributeMaxDynamicSharedMemorySize, ATTN_SMEM);

    // QKV projections (tf32 tensor cores)
    tf32_gemm<<<dim3(DIN / 128, NTOK / 128), 256, GEMM_SMEM>>>(x, Wq, (float*)qp, NTOK, NH * HD, DIN);
    tf32_gemm<<<dim3((NG * HD) / 128, NTOK / 128), 256, GEMM_SMEM>>>(x, Wk, (float*)kp, NTOK, NG * HD, DIN);
    tf32_gemm<<<dim3((NG * HD) / 128, NTOK / 128), 256, GEMM_SMEM>>>(x, Wv, (float*)vp, NTOK, NG * HD, DIN);

    // RMSNorm + RoPE (+ q scale)
    rmsrope_kernel<<<dim3(NTOK, NH), 128>>>((float*)qp, qw, cosb, sinb, NH * HD, QSCALE);
    rmsrope_kernel<<<dim3(NTOK, NG), 128>>>((float*)kp, kw, cosb, sinb, NG * HD, 1.0f);

    // flash attention (fp32)
    attn_kernel<<<dim3(SEQ / BQ, NH, 2), 256, ATTN_SMEM>>>(
        (const float*)qp, (const float*)kp, (const float*)vp, (float*)cp);

    // output projection (tf32 tensor cores)
    tf32_gemm<<<dim3(DIN / 128, NTOK / 128), 256, GEMM_SMEM>>>((const float*)cp, Wo, out, NTOK, NH * HD, DIN);
}

// round 4
// speedup vs baseline: 7.5457x; 5.9084x over previous
#include <cuda_runtime.h>
#include <math.h>
#include <stdint.h>

// Problem dims
#define SEQ   2048
#define DIN   2048
#define NH    16
#define NG    4
#define GSZ   4          // NH / NG
#define HD    128
#define NTOK  4096       // B * SEQ
#define QSCALE 0.08838834764831843f   // 128^-0.5

// ---------------- scratch (device globals; no allocation allowed) -------------
__device__ float g_q[(size_t)NTOK * (NH * HD)];    // 32 MB
__device__ float g_k[(size_t)NTOK * (NG * HD)];    // 8 MB
__device__ float g_v[(size_t)NTOK * (NG * HD)];    // 8 MB
__device__ float g_ctx[(size_t)NTOK * (NH * HD)];  // 32 MB

__device__ __forceinline__ uint32_t f2tf32(float x) {
    uint32_t u;
    asm("cvt.rna.tf32.f32 %0, %1;" : "=r"(u) : "f"(x));
    return u;
}

#define MMA_TF32(d, a, b0, b1)                                              \
    asm volatile(                                                           \
        "mma.sync.aligned.m16n8k8.row.col.f32.tf32.tf32.f32 "               \
        "{%0,%1,%2,%3}, {%4,%5,%6,%7}, {%8,%9}, {%0,%1,%2,%3};"             \
        : "+f"(d[0]), "+f"(d[1]), "+f"(d[2]), "+f"(d[3])                    \
        : "r"(a[0]), "r"(a[1]), "r"(a[2]), "r"(a[3]), "r"(b0), "r"(b1))

// =============================================================================
// TF32 tensor-core GEMM:  C[M,N] = A[M,K] @ B[K,N], row-major fp32 in/out.
// =============================================================================
#define AS_STRIDE 36
#define BS_STRIDE 136
#define AS_ELEMS (128 * AS_STRIDE)
#define BS_ELEMS (32 * BS_STRIDE)
#define GEMM_SMEM ((2 * AS_ELEMS + 2 * BS_ELEMS) * 4)

__global__ __launch_bounds__(256, 1) void tf32_gemm(
    const float* __restrict__ A, const float* __restrict__ B,
    float* __restrict__ C, int M, int N, int K)
{
    extern __shared__ float sm[];
    float* As = sm;
    float* Bs = sm + 2 * AS_ELEMS;

    const int tid  = threadIdx.x;
    const int wid  = tid >> 5;
    const int lane = tid & 31;
    const int r = lane >> 2;
    const int c = lane & 3;
    const int warp_m = wid >> 1;
    const int warp_n = wid & 1;
    const int bx = blockIdx.x, by = blockIdx.y;

    const float* gA = A + (size_t)(by * 128) * K;
    const float* gB = B + bx * 128;

    float acc[2][8][4];
#pragma unroll
    for (int mt = 0; mt < 2; mt++)
#pragma unroll
        for (int nt = 0; nt < 8; nt++)
#pragma unroll
            for (int x = 0; x < 4; x++) acc[mt][nt][x] = 0.f;

    float4 ra[4], rb[4];
    const int nIt = K / 32;

#pragma unroll
    for (int i = 0; i < 4; i++) {
        int idx = tid + i * 256;
        ra[i] = *(const float4*)(gA + (size_t)(idx >> 3) * K + ((idx & 7) * 4));
        rb[i] = *(const float4*)(gB + (size_t)(idx >> 5) * N + ((idx & 31) * 4));
    }
#pragma unroll
    for (int i = 0; i < 4; i++) {
        int idx = tid + i * 256;
        {
            int row = idx >> 3, kc = (idx & 7) * 4;
            float4 v = ra[i];
            float4 w;
            w.x = __uint_as_float(f2tf32(v.x));
            w.y = __uint_as_float(f2tf32(v.y));
            w.z = __uint_as_float(f2tf32(v.z));
            w.w = __uint_as_float(f2tf32(v.w));
            *(float4*)(&As[row * AS_STRIDE + kc]) = w;
        }
        {
            int k = idx >> 5, nc = (idx & 31) * 4;
            float4 v = rb[i];
            float4 w;
            w.x = __uint_as_float(f2tf32(v.x));
            w.y = __uint_as_float(f2tf32(v.y));
            w.z = __uint_as_float(f2tf32(v.z));
            w.w = __uint_as_float(f2tf32(v.w));
            *(float4*)(&Bs[k * BS_STRIDE + nc]) = w;
        }
    }
    __syncthreads();

    for (int it = 0; it < nIt; it++) {
        const int buf = it & 1;
        if (it + 1 < nIt) {
            const int k0 = (it + 1) * 32;
#pragma unroll
            for (int i = 0; i < 4; i++) {
                int idx = tid + i * 256;
                ra[i] = *(const float4*)(gA + (size_t)(idx >> 3) * K + k0 + ((idx & 7) * 4));
                rb[i] = *(const float4*)(gB + (size_t)(k0 + (idx >> 5)) * N + ((idx & 31) * 4));
            }
        }

        const float* a_s = As + buf * AS_ELEMS;
        const float* b_s = Bs + buf * BS_ELEMS;

#pragma unroll
        for (int ks = 0; ks < 4; ks++) {
            const int kc = ks * 8 + c;
            uint32_t af[2][4];
#pragma unroll
            for (int mt = 0; mt < 2; mt++) {
                const int row0 = warp_m * 32 + mt * 16 + r;
                af[mt][0] = __float_as_uint(a_s[row0 * AS_STRIDE + kc]);
                af[mt][1] = __float_as_uint(a_s[(row0 + 8) * AS_STRIDE + kc]);
                af[mt][2] = __float_as_uint(a_s[row0 * AS_STRIDE + kc + 4]);
                af[mt][3] = __float_as_uint(a_s[(row0 + 8) * AS_STRIDE + kc + 4]);
            }
#pragma unroll
            for (int nt = 0; nt < 8; nt++) {
                const int n0 = warp_n * 64 + nt * 8 + r;
                uint32_t b0 = __float_as_uint(b_s[kc * BS_STRIDE + n0]);
                uint32_t b1 = __float_as_uint(b_s[(kc + 4) * BS_STRIDE + n0]);
                MMA_TF32(acc[0][nt], af[0], b0, b1);
                MMA_TF32(acc[1][nt], af[1], b0, b1);
            }
        }

        if (it + 1 < nIt) {
            const int nbuf = buf ^ 1;
            float* a_d = As + nbuf * AS_ELEMS;
            float* b_d = Bs + nbuf * BS_ELEMS;
#pragma unroll
            for (int i = 0; i < 4; i++) {
                int idx = tid + i * 256;
                {
                    int row = idx >> 3, kc2 = (idx & 7) * 4;
                    float4 v = ra[i];
                    float4 w;
                    w.x = __uint_as_float(f2tf32(v.x));
                    w.y = __uint_as_float(f2tf32(v.y));
                    w.z = __uint_as_float(f2tf32(v.z));
                    w.w = __uint_as_float(f2tf32(v.w));
                    *(float4*)(&a_d[row * AS_STRIDE + kc2]) = w;
                }
                {
                    int k = idx >> 5, nc = (idx & 31) * 4;
                    float4 v = rb[i];
                    float4 w;
                    w.x = __uint_as_float(f2tf32(v.x));
                    w.y = __uint_as_float(f2tf32(v.y));
                    w.z = __uint_as_float(f2tf32(v.z));
                    w.w = __uint_as_float(f2tf32(v.w));
                    *(float4*)(&b_d[k * BS_STRIDE + nc]) = w;
                }
            }
            __syncthreads();
        }
    }

#pragma unroll
    for (int mt = 0; mt < 2; mt++) {
#pragma unroll
        for (int nt = 0; nt < 8; nt++) {
            const int row0 = by * 128 + warp_m * 32 + mt * 16 + r;
            const int col  = bx * 128 + warp_n * 64 + nt * 8 + 2 * c;
            float2 v0 = make_float2(acc[mt][nt][0], acc[mt][nt][1]);
            float2 v1 = make_float2(acc[mt][nt][2], acc[mt][nt][3]);
            *(float2*)(C + (size_t)row0 * N + col) = v0;
            *(float2*)(C + (size_t)(row0 + 8) * N + col) = v1;
        }
    }
}

// ---------------- fused RMSNorm + RoPE (+ optional scale), in place ----------
__global__ __launch_bounds__(128) void rmsrope_kernel(
    float* __restrict__ x, const float* __restrict__ w,
    const float* __restrict__ cosb, const float* __restrict__ sinb,
    int rowstride, float outscale)
{
    const int tok = blockIdx.x;
    const int h = blockIdx.y;
    const int d = threadIdx.x;
    const int s = tok & (SEQ - 1);

    float* p = x + (size_t)tok * rowstride + h * HD;
    float v = p[d];

    float ss = v * v;
#pragma unroll
    for (int o = 16; o > 0; o >>= 1) ss += __shfl_xor_sync(0xffffffffu, ss, o);

    __shared__ float partial[4];
    __shared__ float sn[HD];
    if ((d & 31) == 0) partial[d >> 5] = ss;
    __syncthreads();
    float tot = partial[0] + partial[1] + partial[2] + partial[3];
    float rstd = rsqrtf(tot * (1.0f / HD) + 1e-6f);

    float nv = v * rstd * w[d];
    sn[d] = nv;
    __syncthreads();
    float other = sn[d ^ 64];

    float cc = cosb[(size_t)s * HD + d];
    float si = sinb[(size_t)s * HD + d];
    float outv = (d < 64) ? (nv * cc - other * si) : (nv * cc + other * si);
    p[d] = outv * outscale;
}

// =============================================================================
// Tensor-core causal GQA flash attention (tf32 mma, fp32 softmax state).
// BQ=128, BK=64, 8 warps; warp w owns q-rows [w*16, w*16+16) -> warp-local
// softmax (shfl over the 4 c-lanes). Q persistent in smem; P via smem
// (warp-local). Conflict-free strides: Q/K 132, V 136, P 68.
// =============================================================================
#define A_BQ 128
#define A_BK 64
#define QST 132
#define KST 132
#define VST 136
#define PST 68
#define SK_OFF (128 * QST)                 // 16896
#define SV_OFF (SK_OFF + 64 * KST)         // 25344
#define SP_OFF (SV_OFF + 64 * VST)         // 34048
#define ATTN_SMEM ((SP_OFF + 128 * PST) * 4)   // 171008 bytes

__global__ __launch_bounds__(256, 1) void attn_tc_kernel(
    const float* __restrict__ q, const float* __restrict__ k,
    const float* __restrict__ v, float* __restrict__ out)
{
    extern __shared__ float smf[];
    float* sQ = smf;
    float* sK = smf + SK_OFF;
    float* sV = smf + SV_OFF;
    float* sP = smf + SP_OFF;

    const int tid  = threadIdx.x;
    const int wid  = tid >> 5;
    const int lane = tid & 31;
    const int r = lane >> 2;
    const int c = lane & 3;
    const int wm = wid;                      // warp's 16-row slice

    const int qt = gridDim.x - 1 - blockIdx.x;   // heavy tiles first
    const int h  = blockIdx.y;
    const int b  = blockIdx.z;
    const int g  = h >> 2;
    const int qbase = qt * A_BQ;

    const float* qp = q + (size_t)b * SEQ * (NH * HD) + h * HD;
    const float* kp = k + (size_t)b * SEQ * (NG * HD) + g * HD;
    const float* vp = v + (size_t)b * SEQ * (NG * HD) + g * HD;

    // stage Q tile (128 x 128) into smem as tf32
#pragma unroll
    for (int i = 0; i < 16; i++) {
        int idx = tid + i * 256;
        int row = idx >> 5, c4 = (idx & 31) * 4;
        float4 v4 = *(const float4*)(qp + (size_t)(qbase + row) * (NH * HD) + c4);
        float4 w4;
        w4.x = __uint_as_float(f2tf32(v4.x));
        w4.y = __uint_as_float(f2tf32(v4.y));
        w4.z = __uint_as_float(f2tf32(v4.z));
        w4.w = __uint_as_float(f2tf32(v4.w));
        *(float4*)(&sQ[row * QST + c4]) = w4;
    }

    float o[16][4];
#pragma unroll
    for (int nt = 0; nt < 16; nt++)
#pragma unroll
        for (int x = 0; x < 4; x++) o[nt][x] = 0.f;
    float m0 = -1e30f, m1 = -1e30f, l0 = 0.f, l1 = 0.f;

    const int row0g = qbase + wm * 16 + r;       // this thread's global rows
    const int row1g = row0g + 8;

    const int ntiles = 2 * qt + 2;
    for (int kt = 0; kt < ntiles; kt++) {
        const int kbase = kt * A_BK;
        __syncthreads();
        // load K, V tiles (64 x 128) as tf32
#pragma unroll
        for (int i = 0; i < 8; i++) {
            int idx = tid + i * 256;
            int row = idx >> 5, c4 = (idx & 31) * 4;
            float4 k4 = *(const float4*)(kp + (size_t)(kbase + row) * (NG * HD) + c4);
            float4 v4 = *(const float4*)(vp + (size_t)(kbase + row) * (NG * HD) + c4);
            float4 kw, vw;
            kw.x = __uint_as_float(f2tf32(k4.x));
            kw.y = __uint_as_float(f2tf32(k4.y));
            kw.z = __uint_as_float(f2tf32(k4.z));
            kw.w = __uint_as_float(f2tf32(k4.w));
            vw.x = __uint_as_float(f2tf32(v4.x));
            vw.y = __uint_as_float(f2tf32(v4.y));
            vw.z = __uint_as_float(f2tf32(v4.z));
            vw.w = __uint_as_float(f2tf32(v4.w));
            *(float4*)(&sK[row * KST + c4]) = kw;
            *(float4*)(&sV[row * VST + c4]) = vw;
        }
        __syncthreads();

        // warp tiles entirely above the diagonal contribute nothing
        if (qbase + wm * 16 + 15 < kbase) continue;

        // ---- scores: S[16 x 64] = Q_w @ K^T ----
        float sc[8][4];
#pragma unroll
        for (int nt = 0; nt < 8; nt++)
#pragma unroll
            for (int x = 0; x < 4; x++) sc[nt][x] = 0.f;

#pragma unroll
        for (int kk = 0; kk < 16; kk++) {
            const int kc = kk * 8 + c;
            uint32_t a[4];
            a[0] = __float_as_uint(sQ[(wm * 16 + r) * QST + kc]);
            a[1] = __float_as_uint(sQ[(wm * 16 + r + 8) * QST + kc]);
            a[2] = __float_as_uint(sQ[(wm * 16 + r) * QST + kc + 4]);
            a[3] = __float_as_uint(sQ[(wm * 16 + r + 8) * QST + kc + 4]);
#pragma unroll
            for (int nt = 0; nt < 8; nt++) {
                uint32_t b0 = __float_as_uint(sK[(nt * 8 + r) * KST + kc]);
                uint32_t b1 = __float_as_uint(sK[(nt * 8 + r) * KST + kc + 4]);
                MMA_TF32(sc[nt], a, b0, b1);
            }
        }

        // ---- causal mask (only tiles touching the diagonal band) ----
        if (kbase + 63 > qbase + wm * 16) {
#pragma unroll
            for (int nt = 0; nt < 8; nt++) {
                int col = kbase + nt * 8 + 2 * c;
                if (col     > row0g) sc[nt][0] = -1e30f;
                if (col + 1 > row0g) sc[nt][1] = -1e30f;
                if (col     > row1g) sc[nt][2] = -1e30f;
                if (col + 1 > row1g) sc[nt][3] = -1e30f;
            }
        }

        // ---- online softmax (rows r and r+8, reduce over 4 c-lanes) ----
        float tm0 = -1e30f, tm1 = -1e30f;
#pragma unroll
        for (int nt = 0; nt < 8; nt++) {
            tm0 = fmaxf(tm0, fmaxf(sc[nt][0], sc[nt][1]));
            tm1 = fmaxf(tm1, fmaxf(sc[nt][2], sc[nt][3]));
        }
        tm0 = fmaxf(tm0, __shfl_xor_sync(0xffffffffu, tm0, 1));
        tm0 = fmaxf(tm0, __shfl_xor_sync(0xffffffffu, tm0, 2));
        tm1 = fmaxf(tm1, __shfl_xor_sync(0xffffffffu, tm1, 1));
        tm1 = fmaxf(tm1, __shfl_xor_sync(0xffffffffu, tm1, 2));
        float nm0 = fmaxf(m0, tm0);
        float nm1 = fmaxf(m1, tm1);
        float al0 = __expf(m0 - nm0);
        float al1 = __expf(m1 - nm1);
        float ts0 = 0.f, ts1 = 0.f;
#pragma unroll
        for (int nt = 0; nt < 8; nt++) {
            sc[nt][0] = __expf(sc[nt][0] - nm0);
            sc[nt][1] = __expf(sc[nt][1] - nm0);
            sc[nt][2] = __expf(sc[nt][2] - nm1);
            sc[nt][3] = __expf(sc[nt][3] - nm1);
            ts0 += sc[nt][0] + sc[nt][1];
            ts1 += sc[nt][2] + sc[nt][3];
        }
        ts0 += __shfl_xor_sync(0xffffffffu, ts0, 1);
        ts0 += __shfl_xor_sync(0xffffffffu, ts0, 2);
        ts1 += __shfl_xor_sync(0xffffffffu, ts1, 1);
        ts1 += __shfl_xor_sync(0xffffffffu, ts1, 2);
        l0 = l0 * al0 + ts0;
        l1 = l1 * al1 + ts1;
        m0 = nm0;
        m1 = nm1;
#pragma unroll
        for (int nt = 0; nt < 16; nt++) {
            o[nt][0] *= al0;
            o[nt][1] *= al0;
            o[nt][2] *= al1;
            o[nt][3] *= al1;
        }

        // ---- stage P (warp-local) ----
#pragma unroll
        for (int nt = 0; nt < 8; nt++) {
            *(float2*)(&sP[(wm * 16 + r) * PST + nt * 8 + 2 * c]) =
                make_float2(sc[nt][0], sc[nt][1]);
            *(float2*)(&sP[(wm * 16 + r + 8) * PST + nt * 8 + 2 * c]) =
                make_float2(sc[nt][2], sc[nt][3]);
        }
        __syncwarp();

        // ---- O += P @ V ----
#pragma unroll
        for (int kk = 0; kk < 8; kk++) {
            const int kc = kk * 8 + c;
            uint32_t pa[4];
            pa[0] = __float_as_uint(sP[(wm * 16 + r) * PST + kc]);
            pa[1] = __float_as_uint(sP[(wm * 16 + r + 8) * PST + kc]);
            pa[2] = __float_as_uint(sP[(wm * 16 + r) * PST + kc + 4]);
            pa[3] = __float_as_uint(sP[(wm * 16 + r + 8) * PST + kc + 4]);
#pragma unroll
            for (int nt = 0; nt < 16; nt++) {
                uint32_t b0 = __float_as_uint(sV[kc * VST + nt * 8 + r]);
                uint32_t b1 = __float_as_uint(sV[(kc + 4) * VST + nt * 8 + r]);
                MMA_TF32(o[nt], pa, b0, b1);
            }
        }
    }

    // ---- epilogue ----
    const float inv0 = 1.0f / l0;
    const float inv1 = 1.0f / l1;
#pragma unroll
    for (int nt = 0; nt < 16; nt++) {
        const int col = h * HD + nt * 8 + 2 * c;
        *(float2*)(out + (size_t)((size_t)b * SEQ + row0g) * (NH * HD) + col) =
            make_float2(o[nt][0] * inv0, o[nt][1] * inv0);
        *(float2*)(out + (size_t)((size_t)b * SEQ + row1g) * (NH * HD) + col) =
            make_float2(o[nt][2] * inv1, o[nt][3] * inv1);
    }
}

// ---------------- launch -----------------------------------------------------
extern "C" void kernel_launch(void* const* d_in, const int* in_sizes, int n_in,
                              void* d_out, int out_size)
{
    const float* x    = (const float*)d_in[0];
    // d_in[1] = mask (causal, implicit)
    const float* cosb = (const float*)d_in[2];
    const float* sinb = (const float*)d_in[3];
    const float* Wq   = (const float*)d_in[4];
    const float* Wk   = (const float*)d_in[5];
    const float* Wv   = (const float*)d_in[6];
    const float* Wo   = (const float*)d_in[7];
    const float* qw   = (const float*)d_in[8];
    const float* kw   = (const float*)d_in[9];
    float* out = (float*)d_out;

    void *qp, *kp, *vp, *cp;
    cudaGetSymbolAddress(&qp, g_q);
    cudaGetSymbolAddress(&kp, g_k);
    cudaGetSymbolAddress(&vp, g_v);
    cudaGetSymbolAddress(&cp, g_ctx);

    cudaFuncSetAttribute(tf32_gemm, cudaFuncAttributeMaxDynamicSharedMemorySize, GEMM_SMEM);
    cudaFuncSetAttribute(attn_tc_kernel, cudaFuncAttributeMaxDynamicSharedMemorySize, ATTN_SMEM);

    // QKV projections (tf32 tensor cores)
    tf32_gemm<<<dim3(DIN / 128, NTOK / 128), 256, GEMM_SMEM>>>(x, Wq, (float*)qp, NTOK, NH * HD, DIN);
    tf32_gemm<<<dim3((NG * HD) / 128, NTOK / 128), 256, GEMM_SMEM>>>(x, Wk, (float*)kp, NTOK, NG * HD, DIN);
    tf32_gemm<<<dim3((NG * HD) / 128, NTOK / 128), 256, GEMM_SMEM>>>(x, Wv, (float*)vp, NTOK, NG * HD, DIN);

    // RMSNorm + RoPE (+ q scale)
    rmsrope_kernel<<<dim3(NTOK, NH), 128>>>((float*)qp, qw, cosb, sinb, NH * HD, QSCALE);
    rmsrope_kernel<<<dim3(NTOK, NG), 128>>>((float*)kp, kw, cosb, sinb, NG * HD, 1.0f);

    // tensor-core flash attention
    attn_tc_kernel<<<dim3(SEQ / A_BQ, NH, 2), 256, ATTN_SMEM>>>(
        (const float*)qp, (const float*)kp, (const float*)vp, (float*)cp);

    // output projection (tf32 tensor cores)
    tf32_gemm<<<dim3(DIN / 128, NTOK / 128), 256, GEMM_SMEM>>>((const float*)cp, Wo, out, NTOK, NH * HD, DIN);
}

// round 7
// speedup vs baseline: 7.6970x; 1.0200x over previous
#include <cuda_runtime.h>
#include <math.h>
#include <stdint.h>

// Problem dims
#define SEQ   2048
#define DIN   2048
#define NH    16
#define NG    4
#define GSZ   4
#define HD    128
#define NTOK  4096
#define QSCALE 0.08838834764831843f   // 128^-0.5

// ---------------- scratch (device globals; no allocation allowed) -------------
__device__ float g_q[(size_t)NTOK * (NH * HD)];
__device__ float g_k[(size_t)NTOK * (NG * HD)];
__device__ float g_v[(size_t)NTOK * (NG * HD)];
__device__ float g_ctx[(size_t)NTOK * (NH * HD)];

__device__ __forceinline__ uint32_t f2tf32(float x) {
    uint32_t u;
    asm("cvt.rna.tf32.f32 %0, %1;" : "=r"(u) : "f"(x));
    return u;
}

#define MMA_TF32(d, a, b0, b1)                                              \
    asm volatile(                                                           \
        "mma.sync.aligned.m16n8k8.row.col.f32.tf32.tf32.f32 "               \
        "{%0,%1,%2,%3}, {%4,%5,%6,%7}, {%8,%9}, {%0,%1,%2,%3};"             \
        : "+f"(d[0]), "+f"(d[1]), "+f"(d[2]), "+f"(d[3])                    \
        : "r"(a[0]), "r"(a[1]), "r"(a[2]), "r"(a[3]), "r"(b0), "r"(b1))

// =============================================================================
// TF32 tensor-core GEMM core: C[M,N] = A[M,K] @ B[K,N], row-major fp32.
// BM=BN=128, BK=64, 256 threads = 8 warps (4M x 2N), warp tile 32x64.
// Double-buffered smem, register prefetch, rna tf32 conversion at staging.
// A smem: m-major stride 68  (==4 mod 32): a-frag bank (4r+c)%32 distinct.
// B smem: k-major stride 136 (==8 mod 32): b-frag bank (8c+r)%32 distinct.
// =============================================================================
#define AS_STRIDE 68
#define BS_STRIDE 136
#define AS_ELEMS (128 * AS_STRIDE)   // 8704 floats
#define BS_ELEMS (64 * BS_STRIDE)    // 8704 floats
#define GEMM_SMEM ((2 * AS_ELEMS + 2 * BS_ELEMS) * 4)   // 139264 bytes

__device__ __forceinline__ void store_chunkA(float* dst, const float4* ra, int tid) {
#pragma unroll
    for (int i = 0; i < 8; i++) {
        int idx = tid + i * 256;
        int row = idx >> 4, kc = (idx & 15) * 4;
        float4 v = ra[i];
        float4 w;
        w.x = __uint_as_float(f2tf32(v.x));
        w.y = __uint_as_float(f2tf32(v.y));
        w.z = __uint_as_float(f2tf32(v.z));
        w.w = __uint_as_float(f2tf32(v.w));
        *(float4*)(&dst[row * AS_STRIDE + kc]) = w;
    }
}
__device__ __forceinline__ void store_chunkB(float* dst, const float4* rb, int tid) {
#pragma unroll
    for (int i = 0; i < 8; i++) {
        int idx = tid + i * 256;
        int k = idx >> 5, nc = (idx & 31) * 4;
        float4 v = rb[i];
        float4 w;
        w.x = __uint_as_float(f2tf32(v.x));
        w.y = __uint_as_float(f2tf32(v.y));
        w.z = __uint_as_float(f2tf32(v.z));
        w.w = __uint_as_float(f2tf32(v.w));
        *(float4*)(&dst[k * BS_STRIDE + nc]) = w;
    }
}

__device__ __forceinline__ void gemm_core(
    const float* __restrict__ gA, const float* __restrict__ gB,
    float* __restrict__ gC, int N, int K, float* smbase)
{
    float* As = smbase;
    float* Bs = smbase + 2 * AS_ELEMS;

    const int tid  = threadIdx.x;
    const int wid  = tid >> 5;
    const int lane = tid & 31;
    const int r = lane >> 2;
    const int c = lane & 3;
    const int warp_m = wid >> 1;     // 0..3
    const int warp_n = wid & 1;      // 0..1

    float acc[2][8][4];
#pragma unroll
    for (int mt = 0; mt < 2; mt++)
#pragma unroll
        for (int nt = 0; nt < 8; nt++)
#pragma unroll
            for (int x = 0; x < 4; x++) acc[mt][nt][x] = 0.f;

    float4 ra[8], rb[8];
    const int nIt = K / 64;

#pragma unroll
    for (int i = 0; i < 8; i++) {
        int idx = tid + i * 256;
        ra[i] = *(const float4*)(gA + (size_t)(idx >> 4) * K + ((idx & 15) * 4));
        rb[i] = *(const float4*)(gB + (size_t)(idx >> 5) * N + ((idx & 31) * 4));
    }
    store_chunkA(As, ra, tid);
    store_chunkB(Bs, rb, tid);
    __syncthreads();

    for (int it = 0; it < nIt; it++) {
        const int buf = it & 1;
        if (it + 1 < nIt) {
            const int k0 = (it + 1) * 64;
#pragma unroll
            for (int i = 0; i < 8; i++) {
                int idx = tid + i * 256;
                ra[i] = *(const float4*)(gA + (size_t)(idx >> 4) * K + k0 + ((idx & 15) * 4));
                rb[i] = *(const float4*)(gB + (size_t)(k0 + (idx >> 5)) * N + ((idx & 31) * 4));
            }
        }

        const float* a_s = As + buf * AS_ELEMS;
        const float* b_s = Bs + buf * BS_ELEMS;

#pragma unroll
        for (int ks = 0; ks < 8; ks++) {
            const int kc = ks * 8 + c;
            uint32_t af[2][4];
#pragma unroll
            for (int mt = 0; mt < 2; mt++) {
                const int row0 = warp_m * 32 + mt * 16 + r;
                af[mt][0] = __float_as_uint(a_s[row0 * AS_STRIDE + kc]);
                af[mt][1] = __float_as_uint(a_s[(row0 + 8) * AS_STRIDE + kc]);
                af[mt][2] = __float_as_uint(a_s[row0 * AS_STRIDE + kc + 4]);
                af[mt][3] = __float_as_uint(a_s[(row0 + 8) * AS_STRIDE + kc + 4]);
            }
#pragma unroll
            for (int nt = 0; nt < 8; nt++) {
                const int n0 = warp_n * 64 + nt * 8 + r;
                uint32_t b0 = __float_as_uint(b_s[kc * BS_STRIDE + n0]);
                uint32_t b1 = __float_as_uint(b_s[(kc + 4) * BS_STRIDE + n0]);
                MMA_TF32(acc[0][nt], af[0], b0, b1);
                MMA_TF32(acc[1][nt], af[1], b0, b1);
            }
        }

        if (it + 1 < nIt) {
            const int nbuf = buf ^ 1;
            __syncthreads();
            store_chunkA(As + nbuf * AS_ELEMS, ra, tid);
            store_chunkB(Bs + nbuf * BS_ELEMS, rb, tid);
            __syncthreads();
        }
    }

#pragma unroll
    for (int mt = 0; mt < 2; mt++) {
#pragma unroll
        for (int nt = 0; nt < 8; nt++) {
            const int row0 = warp_m * 32 + mt * 16 + r;
            const int col  = warp_n * 64 + nt * 8 + 2 * c;
            *(float2*)(gC + (size_t)row0 * N + col) =
                make_float2(acc[mt][nt][0], acc[mt][nt][1]);
            *(float2*)(gC + (size_t)(row0 + 8) * N + col) =
                make_float2(acc[mt][nt][2], acc[mt][nt][3]);
        }
    }
}

// plain GEMM (used for Wo)
__global__ __launch_bounds__(256, 1) void tf32_gemm(
    const float* __restrict__ A, const float* __restrict__ B,
    float* __restrict__ C, int N, int K)
{
    extern __shared__ float sm[];
    const int bx = blockIdx.x, by = blockIdx.y;
    gemm_core(A + (size_t)(by * 128) * K, B + bx * 128,
              C + (size_t)(by * 128) * N + bx * 128, N, K, sm);
}

// fused QKV projection: grid.x = 16 (Q tiles) + 4 (K) + 4 (V), grid.y = M/128
__global__ __launch_bounds__(256, 1) void tf32_gemm_qkv(
    const float* __restrict__ x,
    const float* __restrict__ Wq, const float* __restrict__ Wk,
    const float* __restrict__ Wv,
    float* __restrict__ q, float* __restrict__ k, float* __restrict__ v)
{
    extern __shared__ float sm[];
    const int bx = blockIdx.x, by = blockIdx.y;
    const float* B;
    float* C;
    int N, xb;
    if (bx < 16)      { B = Wq; C = q; N = 2048; xb = bx; }
    else if (bx < 20) { B = Wk; C = k; N = 512;  xb = bx - 16; }
    else              { B = Wv; C = v; N = 512;  xb = bx - 20; }
    gemm_core(x + (size_t)(by * 128) * DIN, B + xb * 128,
              C + (size_t)(by * 128) * N + xb * 128, N, DIN, sm);
}

// ---------------- fused RMSNorm + RoPE, q & k in one launch ------------------
// grid: (NTOK, 20). blocks y<16 -> q head y; else k head y-16.
__global__ __launch_bounds__(128) void rmsrope_kernel(
    float* __restrict__ q, float* __restrict__ k,
    const float* __restrict__ qw, const float* __restrict__ kw,
    const float* __restrict__ cosb, const float* __restrict__ sinb)
{
    const int tok = blockIdx.x;
    const int hy = blockIdx.y;
    const int d = threadIdx.x;
    const int s = tok & (SEQ - 1);

    float* p;
    const float* w;
    float outscale;
    if (hy < NH) {
        p = q + (size_t)tok * (NH * HD) + hy * HD;
        w = qw;
        outscale = QSCALE;
    } else {
        p = k + (size_t)tok * (NG * HD) + (hy - NH) * HD;
        w = kw;
        outscale = 1.0f;
    }
    float v = p[d];

    float ss = v * v;
#pragma unroll
    for (int o = 16; o > 0; o >>= 1) ss += __shfl_xor_sync(0xffffffffu, ss, o);

    __shared__ float partial[4];
    __shared__ float sn[HD];
    if ((d & 31) == 0) partial[d >> 5] = ss;
    __syncthreads();
    float tot = partial[0] + partial[1] + partial[2] + partial[3];
    float rstd = rsqrtf(tot * (1.0f / HD) + 1e-6f);

    float nv = v * rstd * w[d];
    sn[d] = nv;
    __syncthreads();
    float other = sn[d ^ 64];

    float cc = cosb[(size_t)s * HD + d];
    float si = sinb[(size_t)s * HD + d];
    float outv = (d < 64) ? (nv * cc - other * si) : (nv * cc + other * si);
    p[d] = outv * outscale;
}

// =============================================================================
// Tensor-core causal GQA flash attention (tf32 mma.sync) — unchanged from R3.
// =============================================================================
#define A_BQ 128
#define A_BK 64
#define QST 132
#define KST 132
#define VST 136
#define PST 68
#define SK_OFF (128 * QST)
#define SV_OFF (SK_OFF + 64 * KST)
#define SP_OFF (SV_OFF + 64 * VST)
#define ATTN_SMEM ((SP_OFF + 128 * PST) * 4)

__global__ __launch_bounds__(256, 1) void attn_tc_kernel(
    const float* __restrict__ q, const float* __restrict__ k,
    const float* __restrict__ v, float* __restrict__ out)
{
    extern __shared__ float smf[];
    float* sQ = smf;
    float* sK = smf + SK_OFF;
    float* sV = smf + SV_OFF;
    float* sP = smf + SP_OFF;

    const int tid  = threadIdx.x;
    const int wid  = tid >> 5;
    const int lane = tid & 31;
    const int r = lane >> 2;
    const int c = lane & 3;
    const int wm = wid;

    const int qt = gridDim.x - 1 - blockIdx.x;
    const int h  = blockIdx.y;
    const int b  = blockIdx.z;
    const int g  = h >> 2;
    const int qbase = qt * A_BQ;

    const float* qp = q + (size_t)b * SEQ * (NH * HD) + h * HD;
    const float* kp = k + (size_t)b * SEQ * (NG * HD) + g * HD;
    const float* vp = v + (size_t)b * SEQ * (NG * HD) + g * HD;

#pragma unroll
    for (int i = 0; i < 16; i++) {
        int idx = tid + i * 256;
        int row = idx >> 5, c4 = (idx & 31) * 4;
        float4 v4 = *(const float4*)(qp + (size_t)(qbase + row) * (NH * HD) + c4);
        float4 w4;
        w4.x = __uint_as_float(f2tf32(v4.x));
        w4.y = __uint_as_float(f2tf32(v4.y));
        w4.z = __uint_as_float(f2tf32(v4.z));
        w4.w = __uint_as_float(f2tf32(v4.w));
        *(float4*)(&sQ[row * QST + c4]) = w4;
    }

    float o[16][4];
#pragma unroll
    for (int nt = 0; nt < 16; nt++)
#pragma unroll
        for (int x = 0; x < 4; x++) o[nt][x] = 0.f;
    float m0 = -1e30f, m1 = -1e30f, l0 = 0.f, l1 = 0.f;

    const int row0g = qbase + wm * 16 + r;
    const int row1g = row0g + 8;

    const int ntiles = 2 * qt + 2;
    for (int kt = 0; kt < ntiles; kt++) {
        const int kbase = kt * A_BK;
        __syncthreads();
#pragma unroll
        for (int i = 0; i < 8; i++) {
            int idx = tid + i * 256;
            int row = idx >> 5, c4 = (idx & 31) * 4;
            float4 k4 = *(const float4*)(kp + (size_t)(kbase + row) * (NG * HD) + c4);
            float4 v4 = *(const float4*)(vp + (size_t)(kbase + row) * (NG * HD) + c4);
            float4 kw, vw;
            kw.x = __uint_as_float(f2tf32(k4.x));
            kw.y = __uint_as_float(f2tf32(k4.y));
            kw.z = __uint_as_float(f2tf32(k4.z));
            kw.w = __uint_as_float(f2tf32(k4.w));
            vw.x = __uint_as_float(f2tf32(v4.x));
            vw.y = __uint_as_float(f2tf32(v4.y));
            vw.z = __uint_as_float(f2tf32(v4.z));
            vw.w = __uint_as_float(f2tf32(v4.w));
            *(float4*)(&sK[row * KST + c4]) = kw;
            *(float4*)(&sV[row * VST + c4]) = vw;
        }
        __syncthreads();

        if (qbase + wm * 16 + 15 < kbase) continue;

        float sc[8][4];
#pragma unroll
        for (int nt = 0; nt < 8; nt++)
#pragma unroll
            for (int x = 0; x < 4; x++) sc[nt][x] = 0.f;

#pragma unroll
        for (int kk = 0; kk < 16; kk++) {
            const int kc = kk * 8 + c;
            uint32_t a[4];
            a[0] = __float_as_uint(sQ[(wm * 16 + r) * QST + kc]);
            a[1] = __float_as_uint(sQ[(wm * 16 + r + 8) * QST + kc]);
            a[2] = __float_as_uint(sQ[(wm * 16 + r) * QST + kc + 4]);
            a[3] = __float_as_uint(sQ[(wm * 16 + r + 8) * QST + kc + 4]);
#pragma unroll
            for (int nt = 0; nt < 8; nt++) {
                uint32_t b0 = __float_as_uint(sK[(nt * 8 + r) * KST + kc]);
                uint32_t b1 = __float_as_uint(sK[(nt * 8 + r) * KST + kc + 4]);
                MMA_TF32(sc[nt], a, b0, b1);
            }
        }

        if (kbase + 63 > qbase + wm * 16) {
#pragma unroll
            for (int nt = 0; nt < 8; nt++) {
                int col = kbase + nt * 8 + 2 * c;
                if (col     > row0g) sc[nt][0] = -1e30f;
                if (col + 1 > row0g) sc[nt][1] = -1e30f;
                if (col     > row1g) sc[nt][2] = -1e30f;
                if (col + 1 > row1g) sc[nt][3] = -1e30f;
            }
        }

        float tm0 = -1e30f, tm1 = -1e30f;
#pragma unroll
        for (int nt = 0; nt < 8; nt++) {
            tm0 = fmaxf(tm0, fmaxf(sc[nt][0], sc[nt][1]));
            tm1 = fmaxf(tm1, fmaxf(sc[nt][2], sc[nt][3]));
        }
        tm0 = fmaxf(tm0, __shfl_xor_sync(0xffffffffu, tm0, 1));
        tm0 = fmaxf(tm0, __shfl_xor_sync(0xffffffffu, tm0, 2));
        tm1 = fmaxf(tm1, __shfl_xor_sync(0xffffffffu, tm1, 1));
        tm1 = fmaxf(tm1, __shfl_xor_sync(0xffffffffu, tm1, 2));
        float nm0 = fmaxf(m0, tm0);
        float nm1 = fmaxf(m1, tm1);
        float al0 = __expf(m0 - nm0);
        float al1 = __expf(m1 - nm1);
        float ts0 = 0.f, ts1 = 0.f;
#pragma unroll
        for (int nt = 0; nt < 8; nt++) {
            sc[nt][0] = __expf(sc[nt][0] - nm0);
            sc[nt][1] = __expf(sc[nt][1] - nm0);
            sc[nt][2] = __expf(sc[nt][2] - nm1);
            sc[nt][3] = __expf(sc[nt][3] - nm1);
            ts0 += sc[nt][0] + sc[nt][1];
            ts1 += sc[nt][2] + sc[nt][3];
        }
        ts0 += __shfl_xor_sync(0xffffffffu, ts0, 1);
        ts0 += __shfl_xor_sync(0xffffffffu, ts0, 2);
        ts1 += __shfl_xor_sync(0xffffffffu, ts1, 1);
        ts1 += __shfl_xor_sync(0xffffffffu, ts1, 2);
        l0 = l0 * al0 + ts0;
        l1 = l1 * al1 + ts1;
        m0 = nm0;
        m1 = nm1;
#pragma unroll
        for (int nt = 0; nt < 16; nt++) {
            o[nt][0] *= al0;
            o[nt][1] *= al0;
            o[nt][2] *= al1;
            o[nt][3] *= al1;
        }

#pragma unroll
        for (int nt = 0; nt < 8; nt++) {
            *(float2*)(&sP[(wm * 16 + r) * PST + nt * 8 + 2 * c]) =
                make_float2(sc[nt][0], sc[nt][1]);
            *(float2*)(&sP[(wm * 16 + r + 8) * PST + nt * 8 + 2 * c]) =
                make_float2(sc[nt][2], sc[nt][3]);
        }
        __syncwarp();

#pragma unroll
        for (int kk = 0; kk < 8; kk++) {
            const int kc = kk * 8 + c;
            uint32_t pa[4];
            pa[0] = __float_as_uint(sP[(wm * 16 + r) * PST + kc]);
            pa[1] = __float_as_uint(sP[(wm * 16 + r + 8) * PST + kc]);
            pa[2] = __float_as_uint(sP[(wm * 16 + r) * PST + kc + 4]);
            pa[3] = __float_as_uint(sP[(wm * 16 + r + 8) * PST + kc + 4]);
#pragma unroll
            for (int nt = 0; nt < 16; nt++) {
                uint32_t b0 = __float_as_uint(sV[kc * VST + nt * 8 + r]);
                uint32_t b1 = __float_as_uint(sV[(kc + 4) * VST + nt * 8 + r]);
                MMA_TF32(o[nt], pa, b0, b1);
            }
        }
    }

    const float inv0 = 1.0f / l0;
    const float inv1 = 1.0f / l1;
#pragma unroll
    for (int nt = 0; nt < 16; nt++) {
        const int col = h * HD + nt * 8 + 2 * c;
        *(float2*)(out + (size_t)((size_t)b * SEQ + row0g) * (NH * HD) + col) =
            make_float2(o[nt][0] * inv0, o[nt][1] * inv0);
        *(float2*)(out + (size_t)((size_t)b * SEQ + row1g) * (NH * HD) + col) =
            make_float2(o[nt][2] * inv1, o[nt][3] * inv1);
    }
}

// ---------------- launch -----------------------------------------------------
extern "C" void kernel_launch(void* const* d_in, const int* in_sizes, int n_in,
                              void* d_out, int out_size)
{
    const float* x    = (const float*)d_in[0];
    // d_in[1] = mask (causal, implicit)
    const float* cosb = (const float*)d_in[2];
    const float* sinb = (const float*)d_in[3];
    const float* Wq   = (const float*)d_in[4];
    const float* Wk   = (const float*)d_in[5];
    const float* Wv   = (const float*)d_in[6];
    const float* Wo   = (const float*)d_in[7];
    const float* qw   = (const float*)d_in[8];
    const float* kw   = (const float*)d_in[9];
    float* out = (float*)d_out;

    void *qp, *kp, *vp, *cp;
    cudaGetSymbolAddress(&qp, g_q);
    cudaGetSymbolAddress(&kp, g_k);
    cudaGetSymbolAddress(&vp, g_v);
    cudaGetSymbolAddress(&cp, g_ctx);

    cudaFuncSetAttribute(tf32_gemm, cudaFuncAttributeMaxDynamicSharedMemorySize, GEMM_SMEM);
    cudaFuncSetAttribute(tf32_gemm_qkv, cudaFuncAttributeMaxDynamicSharedMemorySize, GEMM_SMEM);
    cudaFuncSetAttribute(attn_tc_kernel, cudaFuncAttributeMaxDynamicSharedMemorySize, ATTN_SMEM);

    // fused QKV projection (tf32 tensor cores)
    tf32_gemm_qkv<<<dim3(24, NTOK / 128), 256, GEMM_SMEM>>>(
        x, Wq, Wk, Wv, (float*)qp, (float*)kp, (float*)vp);

    // fused RMSNorm + RoPE for q and k in one launch
    rmsrope_kernel<<<dim3(NTOK, NH + NG), 128>>>(
        (float*)qp, (float*)kp, qw, kw, cosb, sinb);

    // tensor-core flash attention
    attn_tc_kernel<<<dim3(SEQ / A_BQ, NH, 2), 256, ATTN_SMEM>>>(
        (const float*)qp, (const float*)kp, (const float*)vp, (float*)cp);

    // output projection
    tf32_gemm<<<dim3(DIN / 128, NTOK / 128), 256, GEMM_SMEM>>>(
        (const float*)cp, Wo, out, DIN, DIN);
}